// round 1
// baseline (speedup 1.0000x reference)
#include <cuda_runtime.h>

// Problem constants
#define T_STEPS 1024
#define Hn      100
#define BB      4     // batch rows per block
#define KC      4     // k-split factor (threads per hidden unit)
#define KK      25    // k elements per thread (Hn / KC)
#define NTHREADS 416  // 104 hidden-slots * 4 kc (13 warps; n>=100 are inert)
#define NWARPS  13

// ---------- f32x2 packed-math helpers (Blackwell FFMA2 path) ----------
__device__ __forceinline__ unsigned long long pack2(float lo, float hi) {
    unsigned long long r;
    asm("mov.b64 %0, {%1, %2};" : "=l"(r) : "f"(lo), "f"(hi));
    return r;
}
__device__ __forceinline__ void unpack2(unsigned long long v, float& lo, float& hi) {
    asm("mov.b64 {%0, %1}, %2;" : "=f"(lo), "=f"(hi) : "l"(v));
}
__device__ __forceinline__ unsigned long long ffma2(unsigned long long a,
                                                    unsigned long long b,
                                                    unsigned long long c) {
    unsigned long long d;
    asm("fma.rn.f32x2 %0, %1, %2, %3;" : "=l"(d) : "l"(a), "l"(b), "l"(c));
    return d;
}
__device__ __forceinline__ unsigned long long fadd2(unsigned long long a,
                                                    unsigned long long b) {
    unsigned long long d;
    asm("add.rn.f32x2 %0, %1, %2;" : "=l"(d) : "l"(a), "l"(b));
    return d;
}

// ---------- fast transcendentals (MUFU ex2/rcp, ~1e-6 rel err) ----------
__device__ __forceinline__ float ex2a(float x) {
    float y; asm("ex2.approx.ftz.f32 %0, %1;" : "=f"(y) : "f"(x)); return y;
}
__device__ __forceinline__ float rcpa(float x) {
    float y; asm("rcp.approx.ftz.f32 %0, %1;" : "=f"(y) : "f"(x)); return y;
}
__device__ __forceinline__ float sigm(float x) {
    // 1 / (1 + 2^(-x*log2e))
    return rcpa(1.0f + ex2a(-1.4426950408889634f * x));
}
__device__ __forceinline__ float tanhx(float x) {
    // 2*sigmoid(2x) - 1
    return fmaf(2.0f, rcpa(1.0f + ex2a(-2.8853900817779268f * x)), -1.0f);
}

// Thread layout: tid = n*4 + kc.
//   n  in [0,104): hidden unit (n>=100 inert, all-zero weights)
//   kc in [0,4):   k-chunk of the 100-wide recurrent dot product; after the
//                  4-lane butterfly reduce, lane kc owns batch b = kc for the
//                  elementwise phase (c-state lives in a register).
// hdup[buf][n*4 + b] holds h[n][b] duplicated into an f32x2 pair so the
// matvec's FFMA2 consumes it with zero packing instructions.
__global__ void __launch_bounds__(NTHREADS, 1)
lstm_persistent_kernel(const float* __restrict__ input,   // [512][1024]
                       const float* __restrict__ W_ih,    // [400] (4H x 1)
                       const float* __restrict__ W_hh,    // [400][100]
                       const float* __restrict__ b_ih,    // [400]
                       const float* __restrict__ b_hh,    // [400]
                       const float* __restrict__ W_out,   // [100]
                       const float* __restrict__ b_out,   // [1]
                       float* __restrict__ out)           // [512][1024]
{
    __shared__ unsigned long long hdup[2][NTHREADS];
    __shared__ float outpart[2][NWARPS * 4];

    const int tid  = threadIdx.x;
    const int n    = tid >> 2;
    const int kc   = tid & 3;
    const int lane = tid & 31;
    const int wid  = tid >> 5;
    const bool valid = (n < Hn);
    const int bbase = blockIdx.x * BB;

    // ---- load recurrent weights into registers (stationary across T) ----
    unsigned long long w01[KK], w23[KK];  // (W_i,W_f) and (W_g,W_o) per k
    float wih_i = 0.f, wih_f = 0.f, wih_g = 0.f, wih_o = 0.f;
    float bi = 0.f, bf = 0.f, bg = 0.f, bo = 0.f, wout = 0.f;
    if (valid) {
        #pragma unroll
        for (int k = 0; k < KK; ++k) {
            const int kk = kc * KK + k;
            const float wi = W_hh[(0 * Hn + n) * Hn + kk];
            const float wf = W_hh[(1 * Hn + n) * Hn + kk];
            const float wg = W_hh[(2 * Hn + n) * Hn + kk];
            const float wo = W_hh[(3 * Hn + n) * Hn + kk];
            w01[k] = pack2(wi, wf);
            w23[k] = pack2(wg, wo);
        }
        wih_i = W_ih[0 * Hn + n];
        wih_f = W_ih[1 * Hn + n];
        wih_g = W_ih[2 * Hn + n];
        wih_o = W_ih[3 * Hn + n];
        bi = b_ih[0 * Hn + n] + b_hh[0 * Hn + n];
        bf = b_ih[1 * Hn + n] + b_hh[1 * Hn + n];
        bg = b_ih[2 * Hn + n] + b_hh[2 * Hn + n];
        bo = b_ih[3 * Hn + n] + b_hh[3 * Hn + n];
        wout = W_out[n];
    } else {
        #pragma unroll
        for (int k = 0; k < KK; ++k) { w01[k] = 0ULL; w23[k] = 0ULL; }
    }
    const float bout = b_out[0];

    hdup[0][tid] = 0ULL;
    hdup[1][tid] = 0ULL;
    float c_state = 0.0f;

    const float* __restrict__ xptr = input + (bbase + kc) * T_STEPS;

    __syncthreads();

    for (int t = 0; t < T_STEPS; ++t) {
        const int p = t & 1;
        const float xv = xptr[t];  // input for batch (bbase+kc), step t

        // ---- recurrent matvec: partial gates over this thread's k-chunk ----
        unsigned long long a00 = 0, a01 = 0, a02 = 0, a03 = 0;
        unsigned long long a10 = 0, a11 = 0, a12 = 0, a13 = 0;
        const ulonglong2* __restrict__ hp =
            reinterpret_cast<const ulonglong2*>(&hdup[p][kc * KK * 4]);
        #pragma unroll
        for (int k = 0; k < KK; ++k) {
            const ulonglong2 hA = hp[2 * k];      // (h,h) for b0, b1
            const ulonglong2 hB = hp[2 * k + 1];  // (h,h) for b2, b3
            a00 = ffma2(w01[k], hA.x, a00);
            a01 = ffma2(w01[k], hA.y, a01);
            a02 = ffma2(w01[k], hB.x, a02);
            a03 = ffma2(w01[k], hB.y, a03);
            a10 = ffma2(w23[k], hA.x, a10);
            a11 = ffma2(w23[k], hA.y, a11);
            a12 = ffma2(w23[k], hB.x, a12);
            a13 = ffma2(w23[k], hB.y, a13);
        }

        // ---- butterfly reduce across the 4 kc lanes ----
        #pragma unroll
        for (int off = 1; off <= 2; off <<= 1) {
            a00 = fadd2(a00, __shfl_xor_sync(0xffffffffu, a00, off));
            a01 = fadd2(a01, __shfl_xor_sync(0xffffffffu, a01, off));
            a02 = fadd2(a02, __shfl_xor_sync(0xffffffffu, a02, off));
            a03 = fadd2(a03, __shfl_xor_sync(0xffffffffu, a03, off));
            a10 = fadd2(a10, __shfl_xor_sync(0xffffffffu, a10, off));
            a11 = fadd2(a11, __shfl_xor_sync(0xffffffffu, a11, off));
            a12 = fadd2(a12, __shfl_xor_sync(0xffffffffu, a12, off));
            a13 = fadd2(a13, __shfl_xor_sync(0xffffffffu, a13, off));
        }

        // ---- this lane takes batch b = kc ----
        const unsigned long long g01 =
            (kc == 0) ? a00 : (kc == 1) ? a01 : (kc == 2) ? a02 : a03;
        const unsigned long long g23 =
            (kc == 0) ? a10 : (kc == 1) ? a11 : (kc == 2) ? a12 : a13;
        float gi, gf, gg, go;
        unpack2(g01, gi, gf);
        unpack2(g23, gg, go);
        gi = fmaf(xv, wih_i, gi + bi);
        gf = fmaf(xv, wih_f, gf + bf);
        gg = fmaf(xv, wih_g, gg + bg);
        go = fmaf(xv, wih_o, go + bo);

        const float ig = sigm(gi);
        const float fg = sigm(gf);
        const float gc = tanhx(gg);
        const float og = sigm(go);
        c_state = fmaf(fg, c_state, ig * gc);
        const float h_ = og * tanhx(c_state);

        // publish h (duplicated pair) for next step's matvec
        hdup[p ^ 1][tid] = pack2(h_, h_);

        // ---- output projection: sum_n h[n][b] * W_out[n] ----
        float po = h_ * wout;  // inert lanes contribute exactly 0
        #pragma unroll
        for (int off = 4; off < 32; off <<= 1)
            po += __shfl_xor_sync(0xffffffffu, po, off);
        if (lane < 4) outpart[p][wid * 4 + lane] = po;

        __syncthreads();

        if (tid < BB) {
            float s = bout;
            #pragma unroll
            for (int w = 0; w < NWARPS; ++w) s += outpart[p][w * 4 + tid];
            out[(bbase + tid) * T_STEPS + t] = s;
        }
    }
}

extern "C" void kernel_launch(void* const* d_in, const int* in_sizes, int n_in,
                              void* d_out, int out_size) {
    (void)in_sizes; (void)n_in; (void)out_size;
    const float* input = (const float*)d_in[0];
    const float* W_ih  = (const float*)d_in[1];
    const float* W_hh  = (const float*)d_in[2];
    const float* b_ih  = (const float*)d_in[3];
    const float* b_hh  = (const float*)d_in[4];
    const float* W_out = (const float*)d_in[5];
    const float* b_out = (const float*)d_in[6];
    float* out = (float*)d_out;

    lstm_persistent_kernel<<<512 / BB, NTHREADS>>>(
        input, W_ih, W_hh, b_ih, b_hh, W_out, b_out, out);
}